// round 1
// baseline (speedup 1.0000x reference)
#include <cuda_runtime.h>
#include <math.h>

#define NS 4096
#define NT 4096
#define TJ 256        // columns per block tile (== blockDim.x)
#define RPB 64        // interior rows per block
#define GX 16         // ceil(4094/256)
#define GY 64         // ceil(4094/64)

__device__ float4  g_coef[NS];
__device__ double  g_partials[GX * GY];

// ---------------------------------------------------------------------------
// Per-row stretching coefficients (fp64, once). Faithful port of
// CubicStretching: hyperbolic depressed-cubic root + metrics chain rule.
// ---------------------------------------------------------------------------
__device__ double solve_cubic(double Q) {
    const double p = 6.0;                 // CHI
    double q  = p * Q;                    // CHI * Q
    double sp = sqrt(p);
    double denom = 2.0 * p * sp / (3.0 * sqrt(3.0));   // = 4*sqrt(2)
    double arg = fabs(q) / denom;
    if (arg < 1.0) arg = 1.0;
    double c = 2.0 * sp * cosh(acosh(arg) / 3.0);
    return (q >= 0.0) ? -c : c;
}

__global__ void precompute_coef() {
    int i = blockIdx.x * blockDim.x + threadIdx.x;
    if (i >= NS) return;
    double C1 = solve_cubic((100.0 - 0.0)   / 30.0);   // (B - 0)/ALPHA_STR
    double C2 = solve_cubic((100.0 - 300.0) / 30.0);   // (B - S_MAX)/ALPHA_STR
    double u  = (double)i / (double)(NS - 1);
    double L  = C2 * u + C1 * (1.0 - u);
    double dL = C2 - C1;
    double S   = 100.0 + 30.0 * (L * L * L / 6.0 + L);
    double dS  = 30.0 * dL * (0.5 * L * L + 1.0);
    double d2S = 30.0 * dL * dL * L;
    double Sn  = S   / 300.0;
    double Su  = dS  / 300.0;
    double Suu = d2S / 300.0;
    float4 c;
    c.x = (float)(1.0 / (Su * Su));            // cA  : V_uu coeff in V_SS
    c.y = (float)(Suu / (Su * Su * Su));       // cB  : V_u  coeff in V_SS
    c.z = (float)(Sn * Sn);                    // s2  : S_norm^2
    c.w = (float)(2.5 * Sn / Su);              // cAS : ALPHA*S_norm/S_u_n
    g_coef[i] = c;
}

// ---------------------------------------------------------------------------
// PDE residual over strict interior. smem 3-row ring, 258-wide with col halo.
// ---------------------------------------------------------------------------
__global__ __launch_bounds__(TJ) void pde_kernel(const float* __restrict__ V) {
    __shared__ float srow[3][TJ + 2];

    const int tid = threadIdx.x;
    const int jb  = 1 + blockIdx.x * TJ;       // first interior column of tile
    const int ib  = 1 + blockIdx.y * RPB;      // first interior row of tile
    const int j   = jb + tid;
    const bool jvalid = (j <= NT - 2);

    // smem idx tid -> global col jb-1+tid ; threads 0,1 also fill idx 256,257
    int jg0 = jb - 1 + tid;                         // max 4095, always in range
    int jg1 = jb - 1 + TJ + tid;                    // only used when tid < 2
    if (jg1 > NT - 1) jg1 = NT - 1;                 // clamp (dead lanes anyway)

    // preload rows ib-1 -> slot 0, ib -> slot 1
    {
        const float* r = V + (size_t)(ib - 1) * NT;
        srow[0][tid] = r[jg0];
        if (tid < 2) srow[0][TJ + tid] = r[jg1];
        r = V + (size_t)ib * NT;
        srow[1][tid] = r[jg0];
        if (tid < 2) srow[1][TJ + tid] = r[jg1];
    }
    __syncthreads();

    float acc = 0.0f;

#pragma unroll 1
    for (int k = 0; k < RPB; k++) {
        const int i = ib + k;
        int inext = i + 1;
        if (inext > NS - 1) inext = NS - 1;          // clamped rows are dead
        const float* r = V + (size_t)inext * NT;
        float a = r[jg0];                             // issue stream load early
        float b = 0.0f;
        if (tid < 2) b = r[jg1];

        const int s_up = k % 3, s_c = (k + 1) % 3, s_dn = (k + 2) % 3;

        if (k > 0) __syncthreads();                   // readers of s_dn done
        srow[s_dn][tid] = a;
        if (tid < 2) srow[s_dn][TJ + tid] = b;
        __syncthreads();

        if (jvalid && i <= NS - 2) {
            const float up = srow[s_up][tid + 1];
            const float c  = srow[s_c ][tid + 1];
            const float dn = srow[s_dn][tid + 1];
            const float lf = srow[s_c ][tid];
            const float rt = srow[s_c ][tid + 2];
            const float4 cf = g_coef[i];

            const float V_u  = (dn - up) * 2047.5f;              // 1/(2*DU)
            const float V_uu = (dn - 2.0f * c + up) * 16769025.0f; // 1/DU^2
            const float V_t  = (rt - lf) * 102375.0f;            // 1/(2*DT)

            float vss = V_uu * cf.x - V_u * cf.y;
            vss = fminf(fmaxf(vss, -100.0f), 100.0f);

            const float res = V_t - cf.z * vss - V_u * cf.w + 2.5f * c;
            acc = fmaf(res, res, acc);
        }
    }

    // warp reduce (float), then block reduce (double)
    for (int o = 16; o; o >>= 1) acc += __shfl_xor_sync(0xffffffffu, acc, o);
    __shared__ double wsum[TJ / 32];
    if ((tid & 31) == 0) wsum[tid >> 5] = (double)acc;
    __syncthreads();
    if (tid == 0) {
        double s = 0.0;
#pragma unroll
        for (int w = 0; w < TJ / 32; w++) s += wsum[w];
        g_partials[blockIdx.y * GX + blockIdx.x] = s;
    }
}

// ---------------------------------------------------------------------------
// Final: sum PDE partials + BC row (S=Smax) + terminal Huber column, combine.
// ---------------------------------------------------------------------------
__global__ __launch_bounds__(256) void final_kernel(const float* __restrict__ V,
                                                    float* __restrict__ out) {
    const int tid = threadIdx.x;
    double pde = 0.0, bc = 0.0, tc = 0.0;

    for (int p = tid; p < GX * GY; p += 256) pde += g_partials[p];

    // far-field BC at row NS-1
    for (int jj = tid; jj < NT; jj += 256) {
        float t      = (float)jj * (1.0f / (float)(NT - 1));
        float target = 1.0f - 100.0f * expf(-0.05f * (1.0f - t)) / 300.0f;
        float d      = V[(size_t)(NS - 1) * NT + jj] - target;
        bc += (double)(d * d);
    }

    // terminal condition at col NT-1 (softplus payoff, Huber)
    const float kos = (float)(100.0 / 300.0);     // K/S_MAX
    for (int ii = tid; ii < NS; ii += 256) {
        float u  = (float)ii * (1.0f / (float)(NS - 1));
        float x  = 50.0f * (u - kos);
        float sp = fmaxf(x, 0.0f) + log1pf(expf(-fabsf(x)));   // stable softplus
        float payoff = sp / 50.0f;
        float d  = V[(size_t)ii * NT + (NT - 1)] - payoff;
        float ad = fabsf(d);
        float h  = (ad < 0.01f) ? 0.5f * d * d : 0.01f * (ad - 0.005f);
        tc += (double)h;
    }

    __shared__ double s1[256], s2[256], s3[256];
    s1[tid] = pde; s2[tid] = bc; s3[tid] = tc;
    __syncthreads();
    for (int o = 128; o; o >>= 1) {
        if (tid < o) { s1[tid] += s1[tid + o]; s2[tid] += s2[tid + o]; s3[tid] += s3[tid + o]; }
        __syncthreads();
    }
    if (tid == 0) {
        const double n_int = (double)(NS - 2) * (double)(NT - 2);   // 16760836
        double total = s1[0] / n_int
                     + 10.0 * s2[0] / (double)NT
                     + 10.0 * s3[0] / (double)NS;
        out[0] = (float)total;
    }
}

extern "C" void kernel_launch(void* const* d_in, const int* in_sizes, int n_in,
                              void* d_out, int out_size) {
    const float* V = (const float*)d_in[0];
    float* out = (float*)d_out;
    precompute_coef<<<(NS + 255) / 256, 256>>>();
    pde_kernel<<<dim3(GX, GY), TJ>>>(V);
    final_kernel<<<1, 256>>>(V, out);
}

// round 3
// speedup vs baseline: 2.2468x; 2.2468x over previous
#include <cuda_runtime.h>
#include <math.h>

#define NS 4096
#define NT 4096
#define RB 32              // interior rows per block chunk
#define WPB 8              // warps per block (256 threads)
#define GX 4               // 4 blocks * 8 warps * 128 cols = 4096 columns
#define GY 128             // 128 chunks * 32 rows >= 4094 interior rows
#define NPART (GX * GY)

__device__ float4 g_coef[NS];
__device__ double g_partials[NPART];

// ---------------------------------------------------------------------------
// Depressed-cubic hyperbolic root (fp64, computed by 2 lanes only).
// ---------------------------------------------------------------------------
__device__ double solve_cubic(double Q) {
    const double p = 6.0;                               // CHI
    double q  = p * Q;
    double sp = sqrt(p);
    double denom = 2.0 * p * sp / (3.0 * sqrt(3.0));    // = 4*sqrt(2)
    double arg = fabs(q) / denom;
    if (arg < 1.0) arg = 1.0;
    double c = 2.0 * sp * cosh(acosh(arg) / 3.0);
    return (q >= 0.0) ? -c : c;
}

__global__ void precompute_coef() {
    __shared__ double sC[2];
    const int t = threadIdx.x;
    if (t < 2) sC[t] = solve_cubic(t == 0 ? (100.0 / 30.0) : (-200.0 / 30.0));
    __syncthreads();
    const float C1 = (float)sC[0], C2 = (float)sC[1];
    const float dL = C2 - C1;
    for (int i = t; i < NS; i += blockDim.x) {
        float u  = (float)i * (1.0f / 4095.0f);
        float L  = C2 * u + C1 * (1.0f - u);
        float S  = 100.0f + 30.0f * (L * L * L * (1.0f / 6.0f) + L);
        float dS = 30.0f * dL * (0.5f * L * L + 1.0f);
        float d2S = 30.0f * dL * dL * L;
        float Sn = S * (1.0f / 300.0f);
        float Su = dS * (1.0f / 300.0f);
        float Suu = d2S * (1.0f / 300.0f);
        float4 c;
        c.x = 1.0f / (Su * Su);              // V_uu coeff of V_SS
        c.y = Suu / (Su * Su * Su);          // V_u  coeff of V_SS
        c.z = Sn * Sn;                       // S_norm^2
        c.w = 2.5f * Sn / Su;                // ALPHA * S_norm / S_u_n
        g_coef[i] = c;
    }
}

// ---------------------------------------------------------------------------
// PDE residual: register-rolling row sweep, float4/lane, shfl column halos,
// zero barriers in the main loop.
// ---------------------------------------------------------------------------
__global__ __launch_bounds__(WPB * 32) void pde_kernel(const float* __restrict__ V) {
    const int tid  = threadIdx.x;
    const int lane = tid & 31;
    const int W    = blockIdx.x * WPB + (tid >> 5);
    const int jbase = W * 128;
    const int j0    = jbase + 4 * lane;
    const bool isL  = (lane == 0);
    const bool isR  = (lane == 31);
    const bool needH = isL || isR;
    int haddr = isL ? (jbase - 1) : (jbase + 128);
    if (haddr < 0) haddr = 0;
    if (haddr > NT - 1) haddr = NT - 1;

    const float m0 = (j0 >= 1) ? 1.0f : 0.0f;           // fails only warp0/lane0
    const float m3 = (j0 + 3 <= NT - 2) ? 1.0f : 0.0f;  // fails only last warp/lane31

    const int ib = 1 + blockIdx.y * RB;                 // first interior row of chunk

    const float* __restrict__ Vj = V + j0;              // column base (vector)
    const float* __restrict__ Vh = V + haddr;           // column base (halo)

    // preload rows ib-1 (up), ib (cc + halo), ib+1 (nxt + halo)
    float4 up = *(const float4*)(Vj + (size_t)(ib - 1) * NT);
    float4 cc = *(const float4*)(Vj + (size_t)ib * NT);
    float hc = needH ? Vh[(size_t)ib * NT] : 0.0f;
    float4 nxt = *(const float4*)(Vj + (size_t)(ib + 1) * NT);
    float hn = needH ? Vh[(size_t)(ib + 1) * NT] : 0.0f;

    float a0 = 0.0f, a1 = 0.0f, a2 = 0.0f, a3 = 0.0f;

#pragma unroll 4
    for (int k = 0; k < RB; k++) {
        const int i = ib + k;
        const float4 dn = nxt;
        const float  hd = hn;

        int rp = i + 2;
        if (rp > NS - 1) rp = NS - 1;
        nxt = *(const float4*)(Vj + (size_t)rp * NT);
        hn = needH ? Vh[(size_t)rp * NT] : 0.0f;

        float lf0 = __shfl_up_sync(0xffffffffu, cc.w, 1);
        float rt3 = __shfl_down_sync(0xffffffffu, cc.x, 1);
        if (isL) lf0 = hc;
        if (isR) rt3 = hc;

        if (i <= NS - 2) {
            const float4 cf = g_coef[i];
            // column 0
            {
                float Vu  = (dn.x - up.x) * 2047.5f;
                float Vuu = (dn.x - 2.0f * cc.x + up.x) * 16769025.0f;
                float Vt  = (cc.y - lf0) * 102375.0f;
                float vss = fminf(fmaxf(Vuu * cf.x - Vu * cf.y, -100.0f), 100.0f);
                float res = Vt - cf.z * vss - Vu * cf.w + 2.5f * cc.x;
                a0 = fmaf(res * m0, res, a0);
            }
            // column 1
            {
                float Vu  = (dn.y - up.y) * 2047.5f;
                float Vuu = (dn.y - 2.0f * cc.y + up.y) * 16769025.0f;
                float Vt  = (cc.z - cc.x) * 102375.0f;
                float vss = fminf(fmaxf(Vuu * cf.x - Vu * cf.y, -100.0f), 100.0f);
                float res = Vt - cf.z * vss - Vu * cf.w + 2.5f * cc.y;
                a1 = fmaf(res, res, a1);
            }
            // column 2
            {
                float Vu  = (dn.z - up.z) * 2047.5f;
                float Vuu = (dn.z - 2.0f * cc.z + up.z) * 16769025.0f;
                float Vt  = (cc.w - cc.y) * 102375.0f;
                float vss = fminf(fmaxf(Vuu * cf.x - Vu * cf.y, -100.0f), 100.0f);
                float res = Vt - cf.z * vss - Vu * cf.w + 2.5f * cc.z;
                a2 = fmaf(res, res, a2);
            }
            // column 3
            {
                float Vu  = (dn.w - up.w) * 2047.5f;
                float Vuu = (dn.w - 2.0f * cc.w + up.w) * 16769025.0f;
                float Vt  = (rt3 - cc.z) * 102375.0f;
                float vss = fminf(fmaxf(Vuu * cf.x - Vu * cf.y, -100.0f), 100.0f);
                float res = Vt - cf.z * vss - Vu * cf.w + 2.5f * cc.w;
                a3 = fmaf(res * m3, res, a3);
            }
        }
        up = cc; cc = dn; hc = hd;
    }

    float acc = (a0 + a1) + (a2 + a3);
    for (int o = 16; o; o >>= 1) acc += __shfl_xor_sync(0xffffffffu, acc, o);
    __shared__ double wsum[WPB];
    if (lane == 0) wsum[tid >> 5] = (double)acc;
    __syncthreads();
    if (tid == 0) {
        double s = 0.0;
#pragma unroll
        for (int w = 0; w < WPB; w++) s += wsum[w];
        g_partials[blockIdx.y * GX + blockIdx.x] = s;
    }
}

// ---------------------------------------------------------------------------
// Final: sum PDE partials + BC row (S=Smax) + terminal Huber column, combine.
// ---------------------------------------------------------------------------
__global__ __launch_bounds__(256) void final_kernel(const float* __restrict__ V,
                                                    float* __restrict__ out) {
    const int tid = threadIdx.x;
    double pde = 0.0, bc = 0.0, tc = 0.0;

#pragma unroll 2
    for (int p = tid; p < NPART; p += 256) pde += g_partials[p];

    // far-field BC at row NS-1 (contiguous 16 KB)
#pragma unroll 8
    for (int jj = tid; jj < NT; jj += 256) {
        float t      = (float)jj * (1.0f / (float)(NT - 1));
        float target = 1.0f - 100.0f * expf(-0.05f * (1.0f - t)) * (1.0f / 300.0f);
        float d      = V[(size_t)(NS - 1) * NT + jj] - target;
        bc += (double)(d * d);
    }

    // terminal condition at col NT-1 (strided; loads independent -> batch)
    const float kos = (float)(100.0 / 300.0);
#pragma unroll 8
    for (int ii = tid; ii < NS; ii += 256) {
        float u  = (float)ii * (1.0f / (float)(NS - 1));
        float x  = 50.0f * (u - kos);
        float sp = fmaxf(x, 0.0f) + log1pf(expf(-fabsf(x)));
        float payoff = sp * (1.0f / 50.0f);
        float d  = V[(size_t)ii * NT + (NT - 1)] - payoff;
        float ad = fabsf(d);
        float h  = (ad < 0.01f) ? 0.5f * d * d : 0.01f * (ad - 0.005f);
        tc += (double)h;
    }

    __shared__ double s1[256], s2[256], s3[256];
    s1[tid] = pde; s2[tid] = bc; s3[tid] = tc;
    __syncthreads();
    for (int o = 128; o; o >>= 1) {
        if (tid < o) { s1[tid] += s1[tid + o]; s2[tid] += s2[tid + o]; s3[tid] += s3[tid + o]; }
        __syncthreads();
    }
    if (tid == 0) {
        const double n_int = (double)(NS - 2) * (double)(NT - 2);
        double total = s1[0] / n_int
                     + 10.0 * s2[0] / (double)NT
                     + 10.0 * s3[0] / (double)NS;
        out[0] = (float)total;
    }
}

extern "C" void kernel_launch(void* const* d_in, const int* in_sizes, int n_in,
                              void* d_out, int out_size) {
    const float* V = (const float*)d_in[0];
    float* out = (float*)d_out;
    precompute_coef<<<1, 128>>>();
    pde_kernel<<<dim3(GX, GY), WPB * 32>>>(V);
    final_kernel<<<1, 256>>>(V, out);
}

// round 4
// speedup vs baseline: 3.3526x; 1.4922x over previous
#include <cuda_runtime.h>
#include <math.h>

#define NS 4096
#define NT 4096
#define RB 32              // interior rows per block chunk
#define WPB 8              // warps per block (256 threads)
#define GX 4               // 4 blocks * 8 warps * 128 cols = 4096 columns
#define GY 128             // 128 chunks * 32 rows >= 4094 interior rows
#define NPART (GX * GY)    // 512 blocks

__device__ double g_partials[NPART];
__device__ unsigned int g_count;   // zero-init at load; reset by last block each call

// fp32 depressed-cubic hyperbolic root (faithful port of reference formula)
__device__ __forceinline__ float cubicf(float Q) {
    float q   = 6.0f * Q;                                   // CHI * Q
    float arg = fabsf(q) * (1.0f / 5.656854249492381f);     // / (4*sqrt(2))
    arg = fmaxf(arg, 1.0f);
    float c = 4.898979485566356f * coshf(acoshf(arg) * (1.0f / 3.0f)); // 2*sqrt(6)*...
    return (q >= 0.0f) ? -c : c;
}

__global__ __launch_bounds__(256, 4) void fused_kernel(const float* __restrict__ V,
                                                       float* __restrict__ out) {
    __shared__ float4 scoef[RB];
    __shared__ double wsum[WPB];
    __shared__ double sbt;          // scaled BC+TC contribution of this block
    __shared__ int    slast;

    const int tid  = threadIdx.x;
    const int lane = tid & 31;
    const int warp = tid >> 5;
    const int bid  = blockIdx.y * GX + blockIdx.x;
    const int W    = blockIdx.x * WPB + warp;
    const int jbase = W * 128;
    const int j0    = jbase + 4 * lane;
    const bool isL  = (lane == 0);
    const bool isR  = (lane == 31);
    const bool needH = isL || isR;
    int haddr = isL ? (jbase - 1) : (jbase + 128);
    haddr = min(max(haddr, 0), NT - 1);

    const float m0 = (j0 >= 1) ? 1.0f : 0.0f;           // only warp0/lane0 col 0
    const float m3 = (j0 + 3 <= NT - 2) ? 1.0f : 0.0f;  // only last warp/lane31 col 4095

    const int ib = 1 + blockIdx.y * RB;                 // first interior row of chunk

    const float* __restrict__ Vj = V + j0;
    const float* __restrict__ Vh = V + haddr;

    // ---- issue preloads immediately (cover the coef computation below) ----
    float4 up = *(const float4*)(Vj + (size_t)(ib - 1) * NT);
    float4 cc = *(const float4*)(Vj + (size_t)ib * NT);
    float  hc = needH ? Vh[(size_t)ib * NT] : 0.0f;
    float4 n1 = *(const float4*)(Vj + (size_t)(ib + 1) * NT);
    float  h1 = needH ? Vh[(size_t)(ib + 1) * NT] : 0.0f;
    const int r2 = min(ib + 2, NS - 1);
    float4 n2 = *(const float4*)(Vj + (size_t)r2 * NT);
    float  h2 = needH ? Vh[(size_t)r2 * NT] : 0.0f;

    // ---- per-block coefficient table (warp 0, overlapped with loads) ----
    if (tid < RB) {
        const float C1 = cubicf(100.0f / 30.0f);        // (B - 0)/ALPHA_STR
        const float C2 = cubicf(-200.0f / 30.0f);       // (B - S_MAX)/ALPHA_STR
        const int   i  = min(ib + tid, NS - 1);
        const float u  = (float)i * (1.0f / 4095.0f);
        const float L  = C2 * u + C1 * (1.0f - u);
        const float dL = C2 - C1;
        const float S   = 100.0f + 30.0f * (L * L * L * (1.0f / 6.0f) + L);
        const float dS  = 30.0f * dL * (0.5f * L * L + 1.0f);
        const float d2S = 30.0f * dL * dL * L;
        const float Sn  = S   * (1.0f / 300.0f);
        const float Su  = dS  * (1.0f / 300.0f);
        const float Suu = d2S * (1.0f / 300.0f);
        float4 c;
        c.x = 1.0f / (Su * Su);              // V_uu coeff of V_SS
        c.y = Suu / (Su * Su * Su);          // V_u  coeff of V_SS
        c.z = Sn * Sn;                       // S_norm^2
        c.w = 2.5f * Sn / Su;                // ALPHA * S_norm / S_u_n
        scoef[tid] = c;
    }
    __syncthreads();

    // ---- main streaming loop: prefetch distance 2, no barriers ----
    float a0 = 0.0f, a1 = 0.0f, a2 = 0.0f, a3 = 0.0f;

#pragma unroll 2
    for (int k = 0; k < RB; k++) {
        const int i = ib + k;
        const float4 dn = n1;  const float hd = h1;
        n1 = n2;               h1 = h2;
        const int rp = min(i + 3, NS - 1);
        n2 = *(const float4*)(Vj + (size_t)rp * NT);
        h2 = needH ? Vh[(size_t)rp * NT] : 0.0f;

        float lf0 = __shfl_up_sync(0xffffffffu, cc.w, 1);
        float rt3 = __shfl_down_sync(0xffffffffu, cc.x, 1);
        if (isL) lf0 = hc;
        if (isR) rt3 = hc;

        if (i <= NS - 2) {
            const float4 cf = scoef[k];
            {   // column 0
                float Vu  = (dn.x - up.x) * 2047.5f;
                float Vuu = (dn.x - 2.0f * cc.x + up.x) * 16769025.0f;
                float Vt  = (cc.y - lf0) * 102375.0f;
                float vss = fminf(fmaxf(Vuu * cf.x - Vu * cf.y, -100.0f), 100.0f);
                float res = Vt - cf.z * vss - Vu * cf.w + 2.5f * cc.x;
                a0 = fmaf(res * m0, res, a0);
            }
            {   // column 1
                float Vu  = (dn.y - up.y) * 2047.5f;
                float Vuu = (dn.y - 2.0f * cc.y + up.y) * 16769025.0f;
                float Vt  = (cc.z - cc.x) * 102375.0f;
                float vss = fminf(fmaxf(Vuu * cf.x - Vu * cf.y, -100.0f), 100.0f);
                float res = Vt - cf.z * vss - Vu * cf.w + 2.5f * cc.y;
                a1 = fmaf(res, res, a1);
            }
            {   // column 2
                float Vu  = (dn.z - up.z) * 2047.5f;
                float Vuu = (dn.z - 2.0f * cc.z + up.z) * 16769025.0f;
                float Vt  = (cc.w - cc.y) * 102375.0f;
                float vss = fminf(fmaxf(Vuu * cf.x - Vu * cf.y, -100.0f), 100.0f);
                float res = Vt - cf.z * vss - Vu * cf.w + 2.5f * cc.z;
                a2 = fmaf(res, res, a2);
            }
            {   // column 3
                float Vu  = (dn.w - up.w) * 2047.5f;
                float Vuu = (dn.w - 2.0f * cc.w + up.w) * 16769025.0f;
                float Vt  = (rt3 - cc.z) * 102375.0f;
                float vss = fminf(fmaxf(Vuu * cf.x - Vu * cf.y, -100.0f), 100.0f);
                float res = Vt - cf.z * vss - Vu * cf.w + 2.5f * cc.w;
                a3 = fmaf(res * m3, res, a3);
            }
        }
        up = cc; cc = dn; hc = hd;
    }

    // ---- BC row + TC column: 8 elements each per block (512 * 8 = 4096) ----
    if (warp == 7) {
        double extra = 0.0;
        if (lane < 8) {
            const int jj = 8 * bid + lane;
            float t      = (float)jj * (1.0f / 4095.0f);
            float target = 1.0f - (100.0f / 300.0f) * expf(-0.05f * (1.0f - t));
            float d      = V[(size_t)(NS - 1) * NT + jj] - target;
            extra = (double)(d * d) * (10.0 / 4096.0);
        } else if (lane < 16) {
            const int ii = 8 * bid + (lane - 8);
            float u  = (float)ii * (1.0f / 4095.0f);
            float x  = 50.0f * (u - (100.0f / 300.0f));
            float sp = fmaxf(x, 0.0f) + log1pf(expf(-fabsf(x)));
            float payoff = sp * (1.0f / 50.0f);
            float d  = V[(size_t)ii * NT + (NT - 1)] - payoff;
            float ad = fabsf(d);
            float h  = (ad < 0.01f) ? 0.5f * d * d : 0.01f * (ad - 0.005f);
            extra = (double)h * (10.0 / 4096.0);
        }
        for (int o = 16; o; o >>= 1) extra += __shfl_xor_sync(0xffffffffu, extra, o);
        if (lane == 0) sbt = extra;
    }

    // ---- block reduction -> double partial ----
    float acc = (a0 + a1) + (a2 + a3);
    for (int o = 16; o; o >>= 1) acc += __shfl_xor_sync(0xffffffffu, acc, o);
    if (lane == 0) wsum[warp] = (double)acc;
    __syncthreads();

    if (tid == 0) {
        double s = 0.0;
#pragma unroll
        for (int w = 0; w < WPB; w++) s += wsum[w];
        const double n_int = (double)(NS - 2) * (double)(NT - 2);
        g_partials[bid] = s / n_int + sbt;
        __threadfence();
        unsigned int old = atomicAdd(&g_count, 1u);
        slast = (old == NPART - 1) ? 1 : 0;
    }
    __syncthreads();

    // ---- last block: final reduction over 512 doubles ----
    if (slast && warp == 0) {
        double s = 0.0;
        for (int p = lane; p < NPART; p += 32) s += g_partials[p];
        for (int o = 16; o; o >>= 1) s += __shfl_xor_sync(0xffffffffu, s, o);
        if (lane == 0) {
            out[0] = (float)s;
            g_count = 0;                     // reset for next graph replay
        }
    }
}

extern "C" void kernel_launch(void* const* d_in, const int* in_sizes, int n_in,
                              void* d_out, int out_size) {
    const float* V = (const float*)d_in[0];
    float* out = (float*)d_out;
    fused_kernel<<<dim3(GX, GY), WPB * 32>>>(V, out);
}

// round 7
// speedup vs baseline: 4.2021x; 1.2534x over previous
#include <cuda_runtime.h>
#include <math.h>

#define NS 4096
#define NT 4096
#define RB 32              // interior rows per block chunk
#define WPB 4              // warps per block (128 threads)
#define GX 8               // 8 blocks * 4 warps * 128 cols = 4096 columns
#define GY 128             // 128 chunks * 32 rows >= 4094 interior rows
#define NPART (GX * GY)    // 1024 blocks

__device__ double g_partials[NPART];
__device__ unsigned int g_count;   // zero-init at load; reset by last block each call

// fp32 depressed-cubic hyperbolic root (faithful port of reference formula)
__device__ __forceinline__ float cubicf(float Q) {
    float q   = 6.0f * Q;                                   // CHI * Q
    float arg = fabsf(q) * (1.0f / 5.656854249492381f);     // / (4*sqrt(2))
    arg = fmaxf(arg, 1.0f);
    float c = 4.898979485566356f * coshf(acoshf(arg) * (1.0f / 3.0f)); // 2*sqrt(6)
    return (q >= 0.0f) ? -c : c;
}

__global__ __launch_bounds__(128, 8) void fused_kernel(const float* __restrict__ V,
                                                       float* __restrict__ out) {
    __shared__ float4 scoef[RB];
    __shared__ double wsum[WPB];
    __shared__ double sbt;
    __shared__ int    slast;

    const int tid  = threadIdx.x;
    const int lane = tid & 31;
    const int warp = tid >> 5;
    const int bid  = blockIdx.y * GX + blockIdx.x;
    const int W    = blockIdx.x * WPB + warp;
    const int jbase = W * 128;
    const int j0    = jbase + 4 * lane;
    const bool isL  = (lane == 0);
    const bool isR  = (lane == 31);
    const bool needH = isL || isR;
    int haddr = isL ? (jbase - 1) : (jbase + 128);
    haddr = min(max(haddr, 0), NT - 1);

    const float m0 = (j0 >= 1) ? 1.0f : 0.0f;           // only block x=0, warp0, lane0
    const float m3 = (j0 + 3 <= NT - 2) ? 1.0f : 0.0f;  // only last warp lane31

    const int ib = 1 + blockIdx.y * RB;                 // first interior row of chunk

    const float* __restrict__ Vj = V + j0;
    const float* __restrict__ Vh = V + haddr;

    // ---- issue preloads immediately (cover the coef computation below) ----
    float4 up = *(const float4*)(Vj + (size_t)(ib - 1) * NT);
    float4 cc = *(const float4*)(Vj + (size_t)ib * NT);
    float  hc = needH ? Vh[(size_t)ib * NT] : 0.0f;
    float4 n1 = *(const float4*)(Vj + (size_t)(ib + 1) * NT);
    float  h1 = needH ? Vh[(size_t)(ib + 1) * NT] : 0.0f;
    const int r2 = min(ib + 2, NS - 1);
    float4 n2 = *(const float4*)(Vj + (size_t)r2 * NT);
    float  h2 = needH ? Vh[(size_t)r2 * NT] : 0.0f;

    // ---- per-block coefficient table (folded constants), overlapped with loads ----
    if (tid < RB) {
        const float C1 = cubicf(100.0f / 30.0f);        // (B - 0)/ALPHA_STR
        const float C2 = cubicf(-200.0f / 30.0f);       // (B - S_MAX)/ALPHA_STR
        const int   i  = min(ib + tid, NS - 1);
        const float u  = (float)i * (1.0f / 4095.0f);
        const float L  = C2 * u + C1 * (1.0f - u);
        const float dL = C2 - C1;
        const float S   = 100.0f + 30.0f * (L * L * L * (1.0f / 6.0f) + L);
        const float dS  = 30.0f * dL * (0.5f * L * L + 1.0f);
        const float d2S = 30.0f * dL * dL * L;
        const float Sn  = S   * (1.0f / 300.0f);
        const float Su  = dS  * (1.0f / 300.0f);
        const float Suu = d2S * (1.0f / 300.0f);
        float4 c;
        c.x = 16769025.0f / (Su * Su);                 // 1/DU^2 folded into V_uu coeff
        c.y = 2047.5f * Suu / (Su * Su * Su);          // 1/(2DU) folded into V_u coeff
        c.z = Sn * Sn;                                 // S_norm^2 (vss stays true scale)
        c.w = 2047.5f * 2.5f * Sn / Su;                // 1/(2DU) * ALPHA * S_norm / S_u_n
        scoef[tid] = c;
    }
    __syncthreads();

    // ---- main streaming loop: prefetch distance 2, no barriers ----
    float a0 = 0.0f, a1 = 0.0f, a2 = 0.0f, a3 = 0.0f;

#pragma unroll 4
    for (int k = 0; k < RB; k++) {
        const int i = ib + k;
        const float4 dn = n1;  const float hd = h1;
        n1 = n2;               h1 = h2;
        const int rp = min(i + 3, NS - 1);
        n2 = *(const float4*)(Vj + (size_t)rp * NT);
        h2 = needH ? Vh[(size_t)rp * NT] : 0.0f;

        float lf0 = __shfl_up_sync(0xffffffffu, cc.w, 1);
        float rt3 = __shfl_down_sync(0xffffffffu, cc.x, 1);
        if (isL) lf0 = hc;
        if (isR) rt3 = hc;

        if (i <= NS - 2) {
            const float4 cf = scoef[k];
            {   // column 0
                float s  = dn.x + up.x;
                float d  = dn.x - up.x;
                float w  = fmaf(-2.0f, cc.x, s);
                float vss = fmaf(-d, cf.y, w * cf.x);
                vss = fminf(fmaxf(vss, -100.0f), 100.0f);
                float res = fmaf(cc.y - lf0, 102375.0f,
                            fmaf(-cf.z, vss,
                            fmaf(-cf.w, d, 2.5f * cc.x)));
                a0 = fmaf(res, res, a0);
            }
            {   // column 1
                float s  = dn.y + up.y;
                float d  = dn.y - up.y;
                float w  = fmaf(-2.0f, cc.y, s);
                float vss = fmaf(-d, cf.y, w * cf.x);
                vss = fminf(fmaxf(vss, -100.0f), 100.0f);
                float res = fmaf(cc.z - cc.x, 102375.0f,
                            fmaf(-cf.z, vss,
                            fmaf(-cf.w, d, 2.5f * cc.y)));
                a1 = fmaf(res, res, a1);
            }
            {   // column 2
                float s  = dn.z + up.z;
                float d  = dn.z - up.z;
                float w  = fmaf(-2.0f, cc.z, s);
                float vss = fmaf(-d, cf.y, w * cf.x);
                vss = fminf(fmaxf(vss, -100.0f), 100.0f);
                float res = fmaf(cc.w - cc.y, 102375.0f,
                            fmaf(-cf.z, vss,
                            fmaf(-cf.w, d, 2.5f * cc.z)));
                a2 = fmaf(res, res, a2);
            }
            {   // column 3
                float s  = dn.w + up.w;
                float d  = dn.w - up.w;
                float w  = fmaf(-2.0f, cc.w, s);
                float vss = fmaf(-d, cf.y, w * cf.x);
                vss = fminf(fmaxf(vss, -100.0f), 100.0f);
                float res = fmaf(rt3 - cc.z, 102375.0f,
                            fmaf(-cf.z, vss,
                            fmaf(-cf.w, d, 2.5f * cc.w)));
                a3 = fmaf(res, res, a3);
            }
        }
        up = cc; cc = dn; hc = hd;
    }

    // boundary columns masked once (iteration-invariant; all values finite)
    a0 *= m0;
    a3 *= m3;

    // ---- BC row + TC column: 4 elements each per block (1024 * 4 = 4096) ----
    if (warp == WPB - 1) {
        double extra = 0.0;
        if (lane < 4) {
            const int jj = 4 * bid + lane;
            if (jj < NT) {
                float t      = (float)jj * (1.0f / 4095.0f);
                float target = 1.0f - (100.0f / 300.0f) * expf(-0.05f * (1.0f - t));
                float d      = V[(size_t)(NS - 1) * NT + jj] - target;
                extra = (double)(d * d) * (10.0 / 4096.0);
            }
        } else if (lane >= 8 && lane < 12) {
            const int ii = 4 * bid + (lane - 8);
            if (ii < NS) {
                float u  = (float)ii * (1.0f / 4095.0f);
                float x  = 50.0f * (u - (100.0f / 300.0f));
                float sp = fmaxf(x, 0.0f) + log1pf(expf(-fabsf(x)));
                float payoff = sp * (1.0f / 50.0f);
                float d  = V[(size_t)ii * NT + (NT - 1)] - payoff;
                float ad = fabsf(d);
                float h  = (ad < 0.01f) ? 0.5f * d * d : 0.01f * (ad - 0.005f);
                extra = (double)h * (10.0 / 4096.0);
            }
        }
        for (int o = 16; o; o >>= 1) extra += __shfl_xor_sync(0xffffffffu, extra, o);
        if (lane == 0) sbt = extra;
    }

    // ---- block reduction -> double partial ----
    float acc = (a0 + a1) + (a2 + a3);
    for (int o = 16; o; o >>= 1) acc += __shfl_xor_sync(0xffffffffu, acc, o);
    if (lane == 0) wsum[warp] = (double)acc;
    __syncthreads();

    if (tid == 0) {
        double s = 0.0;
#pragma unroll
        for (int w = 0; w < WPB; w++) s += wsum[w];
        const double n_int = (double)(NS - 2) * (double)(NT - 2);
        g_partials[bid] = s / n_int + sbt;
        __threadfence();
        unsigned int old = atomicAdd(&g_count, 1u);
        slast = (old == NPART - 1) ? 1 : 0;
    }
    __syncthreads();

    // ---- last block: final reduction over 1024 doubles ----
    if (slast) {
        double s = 0.0;
#pragma unroll
        for (int p = 0; p < NPART / 128; p++) s += g_partials[p * 128 + tid];
        __shared__ double sred[128];
        sred[tid] = s;
        __syncthreads();
        for (int o = 64; o; o >>= 1) {
            if (tid < o) sred[tid] += sred[tid + o];
            __syncthreads();
        }
        if (tid == 0) {
            out[0] = (float)sred[0];
            g_count = 0;                     // reset for next graph replay
        }
    }
}

extern "C" void kernel_launch(void* const* d_in, const int* in_sizes, int n_in,
                              void* d_out, int out_size) {
    const float* V = (const float*)d_in[0];
    float* out = (float*)d_out;
    fused_kernel<<<dim3(GX, GY), WPB * 32>>>(V, out);
}

// round 10
// speedup vs baseline: 4.7140x; 1.1218x over previous
#include <cuda_runtime.h>
#include <math.h>

#define NS 4096
#define NT 4096
#define RB 32              // interior rows per block chunk
#define WPB 4              // warps per block (128 threads)
#define GX 8               // 8 blocks * 4 warps * 128 cols = 4096 columns
#define GY 128             // 128 chunks * 32 rows >= 4094 interior rows
#define NPART (GX * GY)    // 1024 blocks

__device__ double g_partials[NPART];
__device__ unsigned int g_count;   // zero-init at load; reset by last block each call

// fp32 depressed-cubic hyperbolic root (faithful port of reference formula)
__device__ __forceinline__ float cubicf(float Q) {
    float q   = 6.0f * Q;                                   // CHI * Q
    float arg = fabsf(q) * (1.0f / 5.656854249492381f);     // / (4*sqrt(2))
    arg = fmaxf(arg, 1.0f);
    float c = 4.898979485566356f * coshf(acoshf(arg) * (1.0f / 3.0f)); // 2*sqrt(6)
    return (q >= 0.0f) ? -c : c;
}

// one column of the residual; all FD constants pre-folded
__device__ __forceinline__ void col_body(float upv, float ccv, float dnv,
                                         float lf, float rt, float4 cf, float& acc) {
    float s   = dnv + upv;
    float d   = dnv - upv;
    float w   = fmaf(-2.0f, ccv, s);
    float vss = fmaf(-d, cf.y, w * cf.x);
    vss = fminf(fmaxf(vss, -100.0f), 100.0f);
    float res = fmaf(rt - lf, 102375.0f,
                fmaf(-cf.z, vss,
                fmaf(-cf.w, d, 2.5f * ccv)));
    acc = fmaf(res, res, acc);
}

__global__ __launch_bounds__(128, 8) void fused_kernel(const float* __restrict__ V,
                                                       float* __restrict__ out) {
    __shared__ float4 scoef[RB];
    __shared__ double wsum[WPB];
    __shared__ double sbt;
    __shared__ int    slast;

    const int tid  = threadIdx.x;
    const int lane = tid & 31;
    const int warp = tid >> 5;
    const int bid  = blockIdx.y * GX + blockIdx.x;
    const int W    = blockIdx.x * WPB + warp;
    const int jbase = W * 128;
    const int j0    = jbase + 4 * lane;
    const bool isL  = (lane == 0);
    const bool isR  = (lane == 31);
    const bool needH = isL || isR;
    int haddr = isL ? (jbase - 1) : (jbase + 128);
    haddr = min(max(haddr, 0), NT - 1);

    const float m0 = (j0 >= 1) ? 1.0f : 0.0f;
    const float m3 = (j0 + 3 <= NT - 2) ? 1.0f : 0.0f;

    const int ib = 1 + blockIdx.y * RB;                 // first interior row of chunk

    const float* __restrict__ Vj = V + j0;
    const float* __restrict__ Vh = V + haddr;

    // ---- issue preloads immediately (cover the coef computation below) ----
    float4 up = *(const float4*)(Vj + (size_t)(ib - 1) * NT);
    float4 cc = *(const float4*)(Vj + (size_t)ib * NT);
    float  hc = needH ? Vh[(size_t)ib * NT] : 0.0f;
    float4 n1 = *(const float4*)(Vj + (size_t)(ib + 1) * NT);
    float  h1 = needH ? Vh[(size_t)(ib + 1) * NT] : 0.0f;
    const int r2 = min(ib + 2, NS - 1);
    float4 n2 = *(const float4*)(Vj + (size_t)r2 * NT);
    float  h2 = needH ? Vh[(size_t)r2 * NT] : 0.0f;

    // ---- per-block coefficient table (folded constants), overlapped with loads ----
    if (tid < RB) {
        const float C1 = cubicf(100.0f / 30.0f);        // (B - 0)/ALPHA_STR
        const float C2 = cubicf(-200.0f / 30.0f);       // (B - S_MAX)/ALPHA_STR
        const int   i  = min(ib + tid, NS - 1);
        const float u  = (float)i * (1.0f / 4095.0f);
        const float L  = C2 * u + C1 * (1.0f - u);
        const float dL = C2 - C1;
        const float S   = 100.0f + 30.0f * (L * L * L * (1.0f / 6.0f) + L);
        const float dS  = 30.0f * dL * (0.5f * L * L + 1.0f);
        const float d2S = 30.0f * dL * dL * L;
        const float Sn  = S   * (1.0f / 300.0f);
        const float Su  = dS  * (1.0f / 300.0f);
        const float Suu = d2S * (1.0f / 300.0f);
        float4 c;
        c.x = 16769025.0f / (Su * Su);                 // 1/DU^2 folded
        c.y = 2047.5f * Suu / (Su * Su * Su);          // 1/(2DU) folded
        c.z = Sn * Sn;                                 // S_norm^2
        c.w = 2047.5f * 2.5f * Sn / Su;                // 1/(2DU)*ALPHA*Sn/Su
        scoef[tid] = c;
    }
    __syncthreads();

    float a0 = 0.0f, a1 = 0.0f, a2 = 0.0f, a3 = 0.0f;

    if (blockIdx.y < GY - 1) {
        // ================= FAST PATH =================
        // all rows interior (max prefetch row = ib+34 <= 4067 < 4095): no clamps,
        // no validity checks, pure pointer-bump addressing.
        const float* pr = Vj + (size_t)(ib + 3) * NT;   // next row to load
        const float* ph = Vh + (size_t)(ib + 3) * NT;

#pragma unroll 8
        for (int k = 0; k < RB; k++) {
            const float4 dn = n1;  const float hd = h1;
            n1 = n2;               h1 = h2;
            n2 = *(const float4*)pr;
            h2 = needH ? *ph : 0.0f;
            pr += NT;  ph += NT;

            float lf0 = __shfl_up_sync(0xffffffffu, cc.w, 1);
            float rt3 = __shfl_down_sync(0xffffffffu, cc.x, 1);
            if (isL) lf0 = hc;
            if (isR) rt3 = hc;

            const float4 cf = scoef[k];
            col_body(up.x, cc.x, dn.x, lf0,  cc.y, cf, a0);
            col_body(up.y, cc.y, dn.y, cc.x, cc.z, cf, a1);
            col_body(up.z, cc.z, dn.z, cc.y, cc.w, cf, a2);
            col_body(up.w, cc.w, dn.w, cc.z, rt3,  cf, a3);

            up = cc; cc = dn; hc = hd;
        }
    } else {
        // ================= BOUNDARY PATH (8 blocks) =================
#pragma unroll 4
        for (int k = 0; k < RB; k++) {
            const int i = ib + k;
            const float4 dn = n1;  const float hd = h1;
            n1 = n2;               h1 = h2;
            const int rp = min(i + 3, NS - 1);
            n2 = *(const float4*)(Vj + (size_t)rp * NT);
            h2 = needH ? Vh[(size_t)rp * NT] : 0.0f;

            float lf0 = __shfl_up_sync(0xffffffffu, cc.w, 1);
            float rt3 = __shfl_down_sync(0xffffffffu, cc.x, 1);
            if (isL) lf0 = hc;
            if (isR) rt3 = hc;

            if (i <= NS - 2) {
                const float4 cf = scoef[k];
                col_body(up.x, cc.x, dn.x, lf0,  cc.y, cf, a0);
                col_body(up.y, cc.y, dn.y, cc.x, cc.z, cf, a1);
                col_body(up.z, cc.z, dn.z, cc.y, cc.w, cf, a2);
                col_body(up.w, cc.w, dn.w, cc.z, rt3,  cf, a3);
            }
            up = cc; cc = dn; hc = hd;
        }
    }

    // boundary columns masked once (iteration-invariant; all values finite)
    a0 *= m0;
    a3 *= m3;

    // ---- BC row + TC column: 4 elements each per block (1024 * 4 = 4096) ----
    if (warp == WPB - 1) {
        double extra = 0.0;
        if (lane < 4) {
            const int jj = 4 * bid + lane;
            float t      = (float)jj * (1.0f / 4095.0f);
            float target = 1.0f - (100.0f / 300.0f) * expf(-0.05f * (1.0f - t));
            float d      = V[(size_t)(NS - 1) * NT + jj] - target;
            extra = (double)(d * d) * (10.0 / 4096.0);
        } else if (lane >= 8 && lane < 12) {
            const int ii = 4 * bid + (lane - 8);
            float u  = (float)ii * (1.0f / 4095.0f);
            float x  = 50.0f * (u - (100.0f / 300.0f));
            float sp = fmaxf(x, 0.0f) + log1pf(expf(-fabsf(x)));
            float payoff = sp * (1.0f / 50.0f);
            float d  = V[(size_t)ii * NT + (NT - 1)] - payoff;
            float ad = fabsf(d);
            float h  = (ad < 0.01f) ? 0.5f * d * d : 0.01f * (ad - 0.005f);
            extra = (double)h * (10.0 / 4096.0);
        }
        for (int o = 16; o; o >>= 1) extra += __shfl_xor_sync(0xffffffffu, extra, o);
        if (lane == 0) sbt = extra;
    }

    // ---- block reduction -> double partial ----
    float acc = (a0 + a1) + (a2 + a3);
    for (int o = 16; o; o >>= 1) acc += __shfl_xor_sync(0xffffffffu, acc, o);
    if (lane == 0) wsum[warp] = (double)acc;
    __syncthreads();

    if (tid == 0) {
        double s = 0.0;
#pragma unroll
        for (int w = 0; w < WPB; w++) s += wsum[w];
        const double n_int = (double)(NS - 2) * (double)(NT - 2);
        g_partials[bid] = s / n_int + sbt;
        __threadfence();
        unsigned int old = atomicAdd(&g_count, 1u);
        slast = (old == NPART - 1) ? 1 : 0;
    }
    __syncthreads();

    // ---- last block: final reduction over 1024 doubles ----
    if (slast) {
        double s = 0.0;
#pragma unroll
        for (int p = 0; p < NPART / 128; p++) s += g_partials[p * 128 + tid];
        __shared__ double sred[128];
        sred[tid] = s;
        __syncthreads();
        for (int o = 64; o; o >>= 1) {
            if (tid < o) sred[tid] += sred[tid + o];
            __syncthreads();
        }
        if (tid == 0) {
            out[0] = (float)sred[0];
            g_count = 0;                     // reset for next graph replay
        }
    }
}

extern "C" void kernel_launch(void* const* d_in, const int* in_sizes, int n_in,
                              void* d_out, int out_size) {
    const float* V = (const float*)d_in[0];
    float* out = (float*)d_out;
    fused_kernel<<<dim3(GX, GY), WPB * 32>>>(V, out);
}